// round 12
// baseline (speedup 1.0000x reference)
#include <cuda_runtime.h>
#include <cuda_bf16.h>
#include <cstdint>

#define NCTA 128
#define NGRP 64
#define NTH  256
#define B_   64
#define TIN  256
#define V_   64
#define H_   1024
#define TOUT 32
#define NQ0  9
#define NQ1  16
#define CHE  16384   // bf16 elems per packed chunk (32 KB, incl hi/lo)
#define NST  66      // smem n-stride (floats)

typedef __nv_bfloat16 bf16;

// ----------------------------- device scratch ------------------------------
__device__ bf16 g_A0[(size_t)NGRP * NQ0 * CHE];
__device__ bf16 g_A1[(size_t)NGRP * NQ1 * CHE];
__device__ bf16 g_xpk[(size_t)TIN * CHE];
__device__ bf16 g_h0pk[2][8 * CHE];
__device__ bf16 g_h1pk[2][8 * CHE];
__device__ bf16 g_dinpk[CHE];
__device__ float g_h1f[B_ * H_];
__device__ float g_c0[H_ * B_], g_c1[H_ * B_];
__device__ float g_part[NCTA * 2048];      // [cta][g(4)][ch(8)][b(64)]
__device__ unsigned g_pf[NGRP];
__device__ unsigned g_bc = 0;
__device__ volatile unsigned g_bg = 0;

// ------------------------------ grid barrier -------------------------------
__device__ __forceinline__ void grid_barrier() {
    __syncthreads();
    if (threadIdx.x == 0) {
        unsigned gen = g_bg;
        __threadfence();
        unsigned t = atomicAdd(&g_bc, 1u);
        if (t == NCTA - 1) { g_bc = 0; __threadfence(); g_bg = gen + 1; }
        else while (g_bg == gen) { }
        __threadfence();
    }
    __syncthreads();
}

// ------------------------------- helpers -----------------------------------
__device__ __forceinline__ void bfsplit(float v, bf16& h, bf16& l) {
    h = __float2bfloat16(v);
    l = __float2bfloat16(v - __bfloat162float(h));
}
__device__ __forceinline__ float fsig(float x) {
    return __fdividef(1.f, 1.f + __expf(-x));
}
__device__ __forceinline__ float ftanh(float x) {
    return 1.f - __fdividef(2.f, __expf(2.f * x) + 1.f);
}

// fragment-linear B-pack elem index for (k in [0,128), n in [0,64), hl)
__device__ __forceinline__ int bpk_idx(int k, int n, int hl) {
    int s = k >> 4, kk = k & 15;
    int r = kk >> 3, tq = (kk & 7) >> 1, e = kk & 1;
    int f = n >> 3, tl = (n & 7) * 4 + tq;
    return (s * 2 + hl) * 1024 + (f >> 1) * 256 + tl * 8 + (f & 1) * 4 + r * 2 + e;
}
__device__ __forceinline__ void pack_h(bf16* pk, int j, int b, float v) {
    bf16 h, l; bfsplit(v, h, l);
    int ch = j >> 7, k = j & 127;
    pk[ch * CHE + bpk_idx(k, b, 0)] = h;
    pk[ch * CHE + bpk_idx(k, b, 1)] = l;
}
__device__ __forceinline__ void mma16816(float* d, const uint32_t* a, const uint32_t* b) {
    asm volatile(
        "mma.sync.aligned.m16n8k16.row.col.f32.bf16.bf16.f32 "
        "{%0,%1,%2,%3}, {%4,%5,%6,%7}, {%8,%9}, {%0,%1,%2,%3};"
        : "+f"(d[0]), "+f"(d[1]), "+f"(d[2]), "+f"(d[3])
        : "r"(a[0]), "r"(a[1]), "r"(a[2]), "r"(a[3]), "r"(b[0]), "r"(b[1]));
}

// ---------------------------------------------------------------------------
// One LSTM step with global 8-way K-split across the CTA pair (cm, khalf).
// Warp (kq, mh) handles k16-section s = khalf*4+kq, m-tiles {2mh, 2mh+1}.
// Partial gates exchanged with the partner CTA via gmem + pair-sync; each
// CTA epilogues its 8 channels (khalf*8..+7) of group cm.
// ---------------------------------------------------------------------------
__device__ void mma_step(const bf16* __restrict__ Ab, int nq,
                         const bf16* __restrict__ Bfst, int nfst,
                         const bf16* __restrict__ Bsnd,
                         const float* __restrict__ bias,
                         float* __restrict__ cst,
                         bf16* __restrict__ hpk, float* __restrict__ h1f,
                         float* red, float* P,
                         int cm, int khalf, int cta, unsigned target)
{
    const int tid = threadIdx.x, wid = tid >> 5, lane = tid & 31;
    const int kq = wid & 3, mh = wid >> 2;
    const int s = khalf * 4 + kq;
    const int t4 = lane >> 2, tq = lane & 3;

    float acc[2][8][4];
    #pragma unroll
    for (int j = 0; j < 2; j++)
        #pragma unroll
        for (int f = 0; f < 8; f++)
            #pragma unroll
            for (int e = 0; e < 4; e++) acc[j][f][e] = 0.f;

    uint32_t a[2][2][2][4];   // [buf][j][hl][reg]
    uint32_t bb[2][2][8][2];  // [buf][hl][f][reg]

    #define LOADOPS(q, buf) do {                                                \
        const bf16* _A = Ab + (size_t)(q) * CHE;                                \
        const bf16* _B = ((q) < nfst) ? (Bfst + (size_t)(q) * CHE)              \
                                      : (Bsnd + (size_t)((q) - nfst) * CHE);    \
        _Pragma("unroll")                                                       \
        for (int _j = 0; _j < 2; _j++)                                          \
            _Pragma("unroll")                                                   \
            for (int _hl = 0; _hl < 2; _hl++) {                                 \
                uint4 _v = *(const uint4*)(_A +                                 \
                    (((s * 4 + (mh * 2 + _j)) * 2 + _hl) * 256 + lane * 8));    \
                a[buf][_j][_hl][0] = _v.x; a[buf][_j][_hl][1] = _v.y;           \
                a[buf][_j][_hl][2] = _v.z; a[buf][_j][_hl][3] = _v.w;           \
            }                                                                   \
        _Pragma("unroll")                                                       \
        for (int _hl = 0; _hl < 2; _hl++)                                       \
            _Pragma("unroll")                                                   \
            for (int _ii = 0; _ii < 4; _ii++) {                                 \
                uint4 _v = *(const uint4*)(_B +                                 \
                    ((s * 2 + _hl) * 1024 + _ii * 256 + lane * 8));             \
                bb[buf][_hl][2 * _ii][0] = _v.x; bb[buf][_hl][2 * _ii][1] = _v.y; \
                bb[buf][_hl][2 * _ii + 1][0] = _v.z;                            \
                bb[buf][_hl][2 * _ii + 1][1] = _v.w;                            \
            }                                                                   \
    } while (0)

    LOADOPS(0, 0);
    for (int q = 0; q < nq; q++) {
        const int buf = q & 1;
        if (q + 1 < nq) LOADOPS(q + 1, buf ^ 1);
        #pragma unroll
        for (int j = 0; j < 2; j++)
            #pragma unroll
            for (int f = 0; f < 8; f++) {
                mma16816(acc[j][f], a[buf][j][0], bb[buf][0][f]);   // hi*hi
                mma16816(acc[j][f], a[buf][j][0], bb[buf][1][f]);   // hi*lo
                mma16816(acc[j][f], a[buf][j][1], bb[buf][0][f]);   // lo*hi
            }
    }
    #undef LOADOPS

    // per-warp partial -> smem
    #pragma unroll
    for (int j = 0; j < 2; j++) {
        int mb = (mh * 2 + j) * 16 + t4;
        #pragma unroll
        for (int f = 0; f < 8; f++) {
            int n = f * 8 + tq * 2;
            *(float2*)&red[(kq * 64 + mb) * NST + n]     = make_float2(acc[j][f][0], acc[j][f][1]);
            *(float2*)&red[(kq * 64 + mb + 8) * NST + n] = make_float2(acc[j][f][2], acc[j][f][3]);
        }
    }
    __syncthreads();

    // intra-CTA reduce over 4 warps; export partner's 32 rows to gmem
    #pragma unroll
    for (int z = 0; z < 16; z++) {
        int it = tid + z * 256;
        int m = it >> 6, b = it & 63;
        float sv = red[(0 * 64 + m) * NST + b] + red[(1 * 64 + m) * NST + b]
                 + red[(2 * 64 + m) * NST + b] + red[(3 * 64 + m) * NST + b];
        P[m * NST + b] = sv;
        if (((m >> 3) & 1) != khalf) {
            int g = m >> 4, ch = m & 7;
            g_part[cta * 2048 + (g * 8 + ch) * 64 + b] = sv;
        }
    }
    __threadfence();
    __syncthreads();
    if (tid == 0) {
        atomicAdd(&g_pf[cm], 1u);
        while (*(volatile unsigned*)&g_pf[cm] < target) { }
        __threadfence();
    }
    __syncthreads();

    // combine with partner partial + cell update (8 channels x 64 batches)
    const float* pp = g_part + (size_t)((1 - khalf) * NGRP + cm) * 2048;
    #pragma unroll
    for (int z = 0; z < 2; z++) {
        int it = tid + z * 256;
        int ch = it >> 6, b = it & 63;
        int chl = khalf * 8 + ch;
        int j = cm * 16 + chl;
        float g[4];
        #pragma unroll
        for (int gg = 0; gg < 4; gg++)
            g[gg] = P[(gg * 16 + chl) * NST + b] + pp[(gg * 8 + ch) * 64 + b]
                  + bias[gg * 1024 + j];
        float cc = cst[j * 64 + b];
        float cn = fsig(g[1]) * cc + fsig(g[0]) * ftanh(g[2]);
        float hn = fsig(g[3]) * ftanh(cn);
        cst[j * 64 + b] = cn;
        pack_h(hpk, j, b, hn);
        if (h1f) h1f[b * 1024 + j] = hn;
    }
}

// --------------------------------- kernel ----------------------------------
__global__ void __launch_bounds__(NTH, 1)
rnn_kernel(const float* __restrict__ x,
           const float* __restrict__ W0, const float* __restrict__ b0,
           const float* __restrict__ W1, const float* __restrict__ b1,
           const float* __restrict__ Wf, const float* __restrict__ bfv,
           float* __restrict__ out)
{
    extern __shared__ float sm[];
    float* red = sm;                 // [4][64][NST]
    float* P   = sm + 4 * 64 * NST;  // [64][NST]

    const int tid = threadIdx.x, cta = blockIdx.x;
    const int cm = cta & 63, khalf = cta >> 6;
    const int gid = cta * NTH + tid, gs = NCTA * NTH;

    // ---- prologue ----
    if (gid < NGRP) g_pf[gid] = 0;
    for (int i = gid; i < H_ * B_; i += gs) { g_c0[i] = 0.f; g_c1[i] = 0.f; }
    for (int i = gid; i < TIN * 64 * 64; i += gs) {
        int n = i & 63, k = (i >> 6) & 63, tt = i >> 12;
        float v = x[((size_t)n * TIN + tt) * 64 + k];
        bf16 h, l; bfsplit(v, h, l);
        g_xpk[(size_t)tt * CHE + bpk_idx(k, n, 0)] = h;
        g_xpk[(size_t)tt * CHE + bpk_idx(k, n, 1)] = l;
    }
    for (int i = gid; i < TIN * 8192; i += gs) {
        int tt = i >> 13, e = i & 8191;
        g_xpk[(size_t)tt * CHE + 8192 + e] = __float2bfloat16(0.f);
    }
    for (int i = gid; i < 8192; i += gs) g_dinpk[8192 + i] = __float2bfloat16(0.f);
    // W0 -> A0 pack (K layout: [x 0-63 | zeros 64-127 | h 128-1151])
    for (int i = gid; i < NGRP * NQ0 * 8192; i += gs) {
        int p = i & 7, t = (i >> 3) & 31, mt = (i >> 8) & 3, s = (i >> 10) & 7;
        int rest = i >> 13;
        int chk = rest % NQ0, c2 = rest / NQ0;
        int r = p >> 1, e = p & 1;
        int row = (t >> 2) + 8 * (r & 1);
        int koff = 2 * (t & 3) + e + 8 * (r >> 1);
        int m = mt * 16 + row;
        int grow = (m >> 4) * 1024 + c2 * 16 + (m & 15);
        int kg = chk * 128 + s * 16 + koff;
        float w = 0.f;
        if (kg < 64)        w = W0[(size_t)grow * 1088 + kg];
        else if (kg >= 128) w = W0[(size_t)grow * 1088 + kg - 64];
        bf16 h, l; bfsplit(w, h, l);
        size_t base = ((((size_t)(c2 * NQ0 + chk) * 8 + s) * 4 + mt) * 2) * 256 + t * 8 + p;
        g_A0[base] = h;
        g_A0[base + 256] = l;
    }
    // W1 -> A1 pack
    for (int i = gid; i < NGRP * NQ1 * 8192; i += gs) {
        int p = i & 7, t = (i >> 3) & 31, mt = (i >> 8) & 3, s = (i >> 10) & 7;
        int rest = i >> 13;
        int chk = rest & 15, c2 = rest >> 4;
        int r = p >> 1, e = p & 1;
        int row = (t >> 2) + 8 * (r & 1);
        int koff = 2 * (t & 3) + e + 8 * (r >> 1);
        int m = mt * 16 + row;
        int grow = (m >> 4) * 1024 + c2 * 16 + (m & 15);
        int kg = chk * 128 + s * 16 + koff;
        float w = W1[(size_t)grow * 2048 + kg];
        bf16 h, l; bfsplit(w, h, l);
        size_t base = ((((size_t)(c2 * NQ1 + chk) * 8 + s) * 4 + mt) * 2) * 256 + t * 8 + p;
        g_A1[base] = h;
        g_A1[base + 256] = l;
    }
    grid_barrier();

    const bf16* A0c = g_A0 + (size_t)cm * NQ0 * CHE;
    const bf16* A1c = g_A1 + (size_t)cm * NQ1 * CHE;
    unsigned sn = 0;

    // ---- encoder ----
    for (int tt = 0; tt < TIN; tt++) {
        sn++;
        mma_step(A0c, tt == 0 ? 1 : NQ0, g_xpk + (size_t)tt * CHE, 1,
                 g_h0pk[(tt + 1) & 1], b0, g_c0, g_h0pk[tt & 1], (float*)0,
                 red, P, cm, khalf, cta, 2 * sn);
        grid_barrier();
        sn++;
        mma_step(A1c, tt == 0 ? 8 : NQ1, g_h0pk[tt & 1], 8, g_h1pk[(tt + 1) & 1],
                 b1, g_c1, g_h1pk[tt & 1], (float*)0,
                 red, P, cm, khalf, cta, 2 * sn);
        grid_barrier();
    }

    // ---- decoder ----
    for (int s = 0; s < TOUT; s++) {
        const bf16* din = (s == 0) ? (g_xpk + (size_t)(TIN - 1) * CHE) : g_dinpk;
        sn++;
        mma_step(A0c, NQ0, din, 1, g_h0pk[(s + 1) & 1],
                 b0, g_c0, g_h0pk[s & 1], (float*)0,
                 red, P, cm, khalf, cta, 2 * sn);
        grid_barrier();
        sn++;
        mma_step(A1c, NQ1, g_h0pk[s & 1], 8, g_h1pk[(s + 1) & 1],
                 b1, g_c1, g_h1pk[s & 1], g_h1f,
                 red, P, cm, khalf, cta, 2 * sn);
        grid_barrier();
        // projection: out = h1 @ Wf.T + bf  (4096 outs over 128 CTAs)
        {
            int o = cta * 32 + (tid >> 3);
            int v = o >> 6, b = o & 63, ko = tid & 7;
            const float4* hr = (const float4*)(g_h1f + (size_t)b * 1024);
            const float4* wr = (const float4*)(Wf + (size_t)v * 1024);
            float sum = 0.f;
            for (int k = ko; k < 256; k += 8) {
                float4 hv = hr[k], wv = wr[k];
                sum += hv.x * wv.x + hv.y * wv.y + hv.z * wv.z + hv.w * wv.w;
            }
            sum += __shfl_xor_sync(0xffffffffu, sum, 1, 8);
            sum += __shfl_xor_sync(0xffffffffu, sum, 2, 8);
            sum += __shfl_xor_sync(0xffffffffu, sum, 4, 8);
            if (ko == 0) {
                float val = sum + bfv[v];
                out[((size_t)b * TOUT + s) * 64 + v] = val;
                bf16 h, l; bfsplit(val, h, l);
                g_dinpk[bpk_idx(v, b, 0)] = h;
                g_dinpk[bpk_idx(v, b, 1)] = l;
            }
        }
        grid_barrier();
    }
}

// ------------------------------ launch shim --------------------------------
extern "C" void kernel_launch(void* const* d_in, const int* in_sizes, int n_in,
                              void* d_out, int out_size) {
    const float* x  = (const float*)d_in[0];
    const float* W0 = (const float*)d_in[1];
    const float* b0 = (const float*)d_in[2];
    const float* W1 = (const float*)d_in[3];
    const float* b1 = (const float*)d_in[4];
    const float* Wf = (const float*)d_in[5];
    const float* bf = (const float*)d_in[6];
    const int smem_bytes = 5 * 64 * NST * (int)sizeof(float);
    cudaFuncSetAttribute(rnn_kernel, cudaFuncAttributeMaxDynamicSharedMemorySize,
                         smem_bytes);
    rnn_kernel<<<NCTA, NTH, smem_bytes>>>(x, W0, b0, W1, b1, Wf, bf, (float*)d_out);
}

// round 16
// speedup vs baseline: 1.1009x; 1.1009x over previous
#include <cuda_runtime.h>
#include <cuda_bf16.h>
#include <cstdint>

#define NCTA 128
#define NTH  256
#define B_   64
#define TIN  256
#define V_   64
#define H_   1024
#define TOUT 32
#define NQ0  9
#define NQ1  16
#define CHEA 8192    // bf16 elems per packed A chunk (32 rows x 128 k, hi+lo)
#define CHEB 16384   // bf16 elems per packed B chunk (64 n x 128 k, hi+lo)
#define NST  66      // smem n-stride (floats)

typedef __nv_bfloat16 bf16;

// ----------------------------- device scratch ------------------------------
__device__ bf16 g_A0[(size_t)NCTA * NQ0 * CHEA];
__device__ bf16 g_A1[(size_t)NCTA * NQ1 * CHEA];
__device__ bf16 g_xpk[(size_t)TIN * CHEB];
__device__ bf16 g_h0pk[2][8 * CHEB];
__device__ bf16 g_h1pk[2][8 * CHEB];
__device__ bf16 g_dinpk[CHEB];
__device__ float g_h1f[B_ * H_];
__device__ float g_c0[H_ * B_], g_c1[H_ * B_];
__device__ unsigned g_bc = 0;
__device__ volatile unsigned g_bg = 0;

// ------------------------------ grid barrier -------------------------------
__device__ __forceinline__ void grid_barrier() {
    __syncthreads();
    if (threadIdx.x == 0) {
        unsigned gen = g_bg;
        __threadfence();
        unsigned t = atomicAdd(&g_bc, 1u);
        if (t == NCTA - 1) { g_bc = 0; __threadfence(); g_bg = gen + 1; }
        else while (g_bg == gen) { }
        __threadfence();
    }
    __syncthreads();
}

// ------------------------------- helpers -----------------------------------
__device__ __forceinline__ void bfsplit(float v, bf16& h, bf16& l) {
    h = __float2bfloat16(v);
    l = __float2bfloat16(v - __bfloat162float(h));
}
__device__ __forceinline__ float fsig(float x) {
    return __fdividef(1.f, 1.f + __expf(-x));
}
__device__ __forceinline__ float ftanh(float x) {
    return 1.f - __fdividef(2.f, __expf(2.f * x) + 1.f);
}

// fragment-linear B-pack elem index for (k in [0,128), n in [0,64), hl)
__device__ __forceinline__ int bpk_idx(int k, int n, int hl) {
    int s = k >> 4, kk = k & 15;
    int r = kk >> 3, tq = (kk & 7) >> 1, e = kk & 1;
    int f = n >> 3, tl = (n & 7) * 4 + tq;
    return (s * 2 + hl) * 1024 + (f >> 1) * 256 + tl * 8 + (f & 1) * 4 + r * 2 + e;
}
__device__ __forceinline__ void pack_h(bf16* pk, int j, int b, float v) {
    bf16 h, l; bfsplit(v, h, l);
    int ch = j >> 7, k = j & 127;
    pk[ch * CHEB + bpk_idx(k, b, 0)] = h;
    pk[ch * CHEB + bpk_idx(k, b, 1)] = l;
}
__device__ __forceinline__ void mma16816(float* d, const uint32_t* a, const uint32_t* b) {
    asm volatile(
        "mma.sync.aligned.m16n8k16.row.col.f32.bf16.bf16.f32 "
        "{%0,%1,%2,%3}, {%4,%5,%6,%7}, {%8,%9}, {%0,%1,%2,%3};"
        : "+f"(d[0]), "+f"(d[1]), "+f"(d[2]), "+f"(d[3])
        : "r"(a[0]), "r"(a[1]), "r"(a[2]), "r"(a[3]), "r"(b[0]), "r"(b[1]));
}

// ---------------------------------------------------------------------------
// One LSTM step. CTA owns 8 channels (M=32 gate-permuted rows); warp s=wid
// handles k16 section s of each 128-K chunk, both m-tiles. 3-pass bf16-split
// HMMA, fp32 accum, 8-way smem K-reduce, CTA-local cell update.
// ---------------------------------------------------------------------------
__device__ void mma_step(const bf16* __restrict__ Ab, int nq,
                         const bf16* __restrict__ Bfst, int nfst,
                         const bf16* __restrict__ Bsnd,
                         const float* __restrict__ bias,
                         float* __restrict__ cst,
                         bf16* __restrict__ hpk, float* __restrict__ h1f,
                         float* red, float* P2, int cta)
{
    const int tid = threadIdx.x, wid = tid >> 5, lane = tid & 31;
    const int t4 = lane >> 2, tq = lane & 3;

    float acc[2][8][4];
    #pragma unroll
    for (int j = 0; j < 2; j++)
        #pragma unroll
        for (int f = 0; f < 8; f++)
            #pragma unroll
            for (int e = 0; e < 4; e++) acc[j][f][e] = 0.f;

    uint32_t a[2][2][2][4];   // [buf][mt][hl][reg]
    uint32_t bb[2][2][8][2];  // [buf][hl][f][reg]

    #define LOADOPS(q, buf) do {                                                \
        const bf16* _A = Ab + (size_t)(q) * CHEA;                               \
        const bf16* _B = ((q) < nfst) ? (Bfst + (size_t)(q) * CHEB)             \
                                      : (Bsnd + (size_t)((q) - nfst) * CHEB);   \
        _Pragma("unroll")                                                       \
        for (int _mt = 0; _mt < 2; _mt++)                                       \
            _Pragma("unroll")                                                   \
            for (int _hl = 0; _hl < 2; _hl++) {                                 \
                uint4 _v = *(const uint4*)(_A +                                 \
                    (((wid * 2 + _mt) * 2 + _hl) * 256 + lane * 8));            \
                a[buf][_mt][_hl][0] = _v.x; a[buf][_mt][_hl][1] = _v.y;         \
                a[buf][_mt][_hl][2] = _v.z; a[buf][_mt][_hl][3] = _v.w;         \
            }                                                                   \
        _Pragma("unroll")                                                       \
        for (int _hl = 0; _hl < 2; _hl++)                                       \
            _Pragma("unroll")                                                   \
            for (int _ii = 0; _ii < 4; _ii++) {                                 \
                uint4 _v = *(const uint4*)(_B +                                 \
                    ((wid * 2 + _hl) * 1024 + _ii * 256 + lane * 8));           \
                bb[buf][_hl][2 * _ii][0] = _v.x; bb[buf][_hl][2 * _ii][1] = _v.y; \
                bb[buf][_hl][2 * _ii + 1][0] = _v.z;                            \
                bb[buf][_hl][2 * _ii + 1][1] = _v.w;                            \
            }                                                                   \
    } while (0)

    LOADOPS(0, 0);
    for (int q = 0; q < nq; q++) {
        const int buf = q & 1;
        if (q + 1 < nq) LOADOPS(q + 1, buf ^ 1);
        #pragma unroll
        for (int j = 0; j < 2; j++)
            #pragma unroll
            for (int f = 0; f < 8; f++) {
                mma16816(acc[j][f], a[buf][j][0], bb[buf][0][f]);   // hi*hi
                mma16816(acc[j][f], a[buf][j][0], bb[buf][1][f]);   // hi*lo
                mma16816(acc[j][f], a[buf][j][1], bb[buf][0][f]);   // lo*hi
            }
    }
    #undef LOADOPS

    // per-warp partial -> smem: red[(wid*32 + m)*NST + n]
    #pragma unroll
    for (int j = 0; j < 2; j++) {
        int mb = wid * 32 + j * 16 + t4;
        #pragma unroll
        for (int f = 0; f < 8; f++) {
            int n = f * 8 + tq * 2;
            *(float2*)&red[mb * NST + n]       = make_float2(acc[j][f][0], acc[j][f][1]);
            *(float2*)&red[(mb + 8) * NST + n] = make_float2(acc[j][f][2], acc[j][f][3]);
        }
    }
    __syncthreads();

    // reduce 8 partials -> P2[32][NST]
    #pragma unroll
    for (int z = 0; z < 8; z++) {
        int it = tid + z * 256;
        int m = it >> 6, b = it & 63;
        float sv = 0.f;
        #pragma unroll
        for (int s2 = 0; s2 < 8; s2++) sv += red[(s2 * 32 + m) * NST + b];
        P2[m * NST + b] = sv;
    }
    __syncthreads();

    // cell update: 8 channels x 64 batches, CTA-local
    #pragma unroll
    for (int z = 0; z < 2; z++) {
        int it = tid + z * 256;
        int ch = it >> 6, b = it & 63;
        int j = cta * 8 + ch;
        float g[4];
        #pragma unroll
        for (int gg = 0; gg < 4; gg++)
            g[gg] = P2[(gg * 8 + ch) * NST + b] + bias[gg * 1024 + j];
        float cc = cst[j * 64 + b];
        float cn = fsig(g[1]) * cc + fsig(g[0]) * ftanh(g[2]);
        float hn = fsig(g[3]) * ftanh(cn);
        cst[j * 64 + b] = cn;
        pack_h(hpk, j, b, hn);
        if (h1f) h1f[b * 1024 + j] = hn;
    }
}

// --------------------------------- kernel ----------------------------------
__global__ void __launch_bounds__(NTH, 1)
rnn_kernel(const float* __restrict__ x,
           const float* __restrict__ W0, const float* __restrict__ b0,
           const float* __restrict__ W1, const float* __restrict__ b1,
           const float* __restrict__ Wf, const float* __restrict__ bfv,
           float* __restrict__ out)
{
    extern __shared__ float sm[];
    float* red = sm;                 // [8*32][NST]
    float* P2  = sm + 8 * 32 * NST;  // [32][NST]

    const int tid = threadIdx.x, cta = blockIdx.x;
    const int gid = cta * NTH + tid, gs = NCTA * NTH;

    // ---- prologue ----
    for (int i = gid; i < H_ * B_; i += gs) { g_c0[i] = 0.f; g_c1[i] = 0.f; }
    for (int i = gid; i < TIN * 64 * 64; i += gs) {
        int n = i & 63, k = (i >> 6) & 63, tt = i >> 12;
        float v = x[((size_t)n * TIN + tt) * 64 + k];
        bf16 h, l; bfsplit(v, h, l);
        g_xpk[(size_t)tt * CHEB + bpk_idx(k, n, 0)] = h;
        g_xpk[(size_t)tt * CHEB + bpk_idx(k, n, 1)] = l;
    }
    for (int i = gid; i < TIN * 8192; i += gs) {
        int tt = i >> 13, e = i & 8191;
        g_xpk[(size_t)tt * CHEB + 8192 + e] = __float2bfloat16(0.f);
    }
    for (int i = gid; i < 8192; i += gs) g_dinpk[8192 + i] = __float2bfloat16(0.f);
    // W0 -> A0 pack (K layout: [x 0-63 | zeros 64-127 | h 128-1151])
    // A chunk layout: [s(8)][mt(2)][hl(2)][256]
    for (int i = gid; i < NCTA * NQ0 * 4096; i += gs) {
        int p = i & 7, t = (i >> 3) & 31, mt = (i >> 8) & 1, s = (i >> 9) & 7;
        int rest = i >> 12;
        int chk = rest % NQ0, c2 = rest / NQ0;
        int r = p >> 1, e = p & 1;
        int row = (t >> 2) + 8 * (r & 1);
        int koff = 2 * (t & 3) + e + 8 * (r >> 1);
        int m = mt * 16 + row;
        int grow = (m >> 3) * 1024 + c2 * 8 + (m & 7);
        int kg = chk * 128 + s * 16 + koff;
        float w = 0.f;
        if (kg < 64)        w = W0[(size_t)grow * 1088 + kg];
        else if (kg >= 128) w = W0[(size_t)grow * 1088 + kg - 64];
        bf16 h, l; bfsplit(w, h, l);
        size_t base = ((((size_t)(c2 * NQ0 + chk) * 8 + s) * 2 + mt) * 2) * 256 + t * 8 + p;
        g_A0[base] = h;
        g_A0[base + 256] = l;
    }
    // W1 -> A1 pack
    for (int i = gid; i < NCTA * NQ1 * 4096; i += gs) {
        int p = i & 7, t = (i >> 3) & 31, mt = (i >> 8) & 1, s = (i >> 9) & 7;
        int rest = i >> 12;
        int chk = rest & 15, c2 = rest >> 4;
        int r = p >> 1, e = p & 1;
        int row = (t >> 2) + 8 * (r & 1);
        int koff = 2 * (t & 3) + e + 8 * (r >> 1);
        int m = mt * 16 + row;
        int grow = (m >> 3) * 1024 + c2 * 8 + (m & 7);
        int kg = chk * 128 + s * 16 + koff;
        float w = W1[(size_t)grow * 2048 + kg];
        bf16 h, l; bfsplit(w, h, l);
        size_t base = ((((size_t)(c2 * NQ1 + chk) * 8 + s) * 2 + mt) * 2) * 256 + t * 8 + p;
        g_A1[base] = h;
        g_A1[base + 256] = l;
    }
    grid_barrier();

    const bf16* A0c = g_A0 + (size_t)cta * NQ0 * CHEA;
    const bf16* A1c = g_A1 + (size_t)cta * NQ1 * CHEA;

    // ---- encoder ----
    for (int tt = 0; tt < TIN; tt++) {
        mma_step(A0c, tt == 0 ? 1 : NQ0, g_xpk + (size_t)tt * CHEB, 1,
                 g_h0pk[(tt + 1) & 1], b0, g_c0, g_h0pk[tt & 1], (float*)0,
                 red, P2, cta);
        grid_barrier();
        mma_step(A1c, tt == 0 ? 8 : NQ1, g_h0pk[tt & 1], 8, g_h1pk[(tt + 1) & 1],
                 b1, g_c1, g_h1pk[tt & 1], (float*)0,
                 red, P2, cta);
        grid_barrier();
    }

    // ---- decoder ----
    for (int s = 0; s < TOUT; s++) {
        const bf16* din = (s == 0) ? (g_xpk + (size_t)(TIN - 1) * CHEB) : g_dinpk;
        mma_step(A0c, NQ0, din, 1, g_h0pk[(s + 1) & 1],
                 b0, g_c0, g_h0pk[s & 1], (float*)0, red, P2, cta);
        grid_barrier();
        mma_step(A1c, NQ1, g_h0pk[s & 1], 8, g_h1pk[(s + 1) & 1],
                 b1, g_c1, g_h1pk[s & 1], g_h1f, red, P2, cta);
        grid_barrier();
        // projection: out = h1 @ Wf.T + bf  (4096 outs over 128 CTAs)
        {
            int o = cta * 32 + (tid >> 3);
            int v = o >> 6, b = o & 63, ko = tid & 7;
            const float4* hr = (const float4*)(g_h1f + (size_t)b * 1024);
            const float4* wr = (const float4*)(Wf + (size_t)v * 1024);
            float sum = 0.f;
            for (int k = ko; k < 256; k += 8) {
                float4 hv = hr[k], wv = wr[k];
                sum += hv.x * wv.x + hv.y * wv.y + hv.z * wv.z + hv.w * wv.w;
            }
            sum += __shfl_xor_sync(0xffffffffu, sum, 1, 8);
            sum += __shfl_xor_sync(0xffffffffu, sum, 2, 8);
            sum += __shfl_xor_sync(0xffffffffu, sum, 4, 8);
            if (ko == 0) {
                float val = sum + bfv[v];
                out[((size_t)b * TOUT + s) * 64 + v] = val;
                bf16 h, l; bfsplit(val, h, l);
                g_dinpk[bpk_idx(v, b, 0)] = h;
                g_dinpk[bpk_idx(v, b, 1)] = l;
            }
        }
        grid_barrier();
    }
}

// ------------------------------ launch shim --------------------------------
extern "C" void kernel_launch(void* const* d_in, const int* in_sizes, int n_in,
                              void* d_out, int out_size) {
    const float* x  = (const float*)d_in[0];
    const float* W0 = (const float*)d_in[1];
    const float* b0 = (const float*)d_in[2];
    const float* W1 = (const float*)d_in[3];
    const float* b1 = (const float*)d_in[4];
    const float* Wf = (const float*)d_in[5];
    const float* bf = (const float*)d_in[6];
    const int smem_bytes = (8 * 32 + 32) * NST * (int)sizeof(float);
    cudaFuncSetAttribute(rnn_kernel, cudaFuncAttributeMaxDynamicSharedMemorySize,
                         smem_bytes);
    rnn_kernel<<<NCTA, NTH, smem_bytes>>>(x, W0, b0, W1, b1, Wf, bf, (float*)d_out);
}